// round 1
// baseline (speedup 1.0000x reference)
#include <cuda_runtime.h>
#include <cstdint>

#define NN 100000
#define NE 3200000
#define NG 64

// ---------------- scratch (static device globals; no allocation) ----------------
__device__ float g_deg[NN];
__device__ float g_dinv[NN];
__device__ float g_norm[NE];
__device__ float g_agg1[NN * 16];
__device__ float g_h1[NN * 16];
__device__ float g_agg2[NN * 16];
__device__ float g_h2[NN * 64];
__device__ float g_agg3[NN * 64];
__device__ float g_h3[NN * 256];
__device__ float g_sums[NG * 256];
__device__ float g_cnt[NG];

__device__ __forceinline__ float silu(float v) {
    return v / (1.0f + __expf(-v));
}

__device__ __forceinline__ void redAdd4(float* addr, float a, float b, float c, float d) {
    asm volatile("red.global.add.v4.f32 [%0], {%1,%2,%3,%4};"
                 :: "l"(addr), "f"(a), "f"(b), "f"(c), "f"(d) : "memory");
}

// ---------------- degree / norm precompute ----------------
__global__ void k_deg_init(float* deg, int n) {
    int i = blockIdx.x * blockDim.x + threadIdx.x;
    if (i < n) deg[i] = 1.0f;  // self-loop weight
}

__global__ void k_deg_acc(const int* __restrict__ dst, const float* __restrict__ ew,
                          float* deg, int e) {
    int i = blockIdx.x * blockDim.x + threadIdx.x;
    if (i < e) atomicAdd(&deg[dst[i]], ew[i]);
}

__global__ void k_dinv(const float* __restrict__ deg, float* dinv, int n) {
    int i = blockIdx.x * blockDim.x + threadIdx.x;
    if (i < n) dinv[i] = rsqrtf(deg[i]);
}

__global__ void k_norm(const int* __restrict__ src, const int* __restrict__ dst,
                       const float* __restrict__ ew, const float* __restrict__ dinv,
                       float* norm, int e) {
    int i = blockIdx.x * blockDim.x + threadIdx.x;
    if (i < e) norm[i] = dinv[src[i]] * ew[i] * dinv[dst[i]];
}

// agg1 = x * dinv^2  (self-loop init for layer 1, dim 16 -> 4 float4 per node)
__global__ void k_agg1_init(const float* __restrict__ x, const float* __restrict__ dinv,
                            float* agg, int n) {
    int idx = blockIdx.x * blockDim.x + threadIdx.x;  // over n*4 float4
    if (idx >= n * 4) return;
    int node = idx >> 2;
    float d = dinv[node];
    float d2 = d * d;
    float4 v = ((const float4*)x)[idx];
    float4 o = {v.x * d2, v.y * d2, v.z * d2, v.w * d2};
    ((float4*)agg)[idx] = o;
}

// ---------------- edge scatter: agg[dst] += norm * h[src] ----------------
// dim 16: 4 lanes per edge (one float4 each)
__global__ void k_scatter16(const int* __restrict__ src, const int* __restrict__ dst,
                            const float* __restrict__ norm, const float* __restrict__ h,
                            float* agg, int e) {
    int tid = blockIdx.x * blockDim.x + threadIdx.x;
    if (tid >= e * 4) return;
    int ed = tid >> 2;
    int j = tid & 3;
    int s = __ldg(&src[ed]);
    int d = __ldg(&dst[ed]);
    float w = __ldg(&norm[ed]);
    float4 v = ((const float4*)h)[s * 4 + j];
    redAdd4(agg + (size_t)d * 16 + j * 4, v.x * w, v.y * w, v.z * w, v.w * w);
}

// dim 64: 16 lanes per edge
__global__ void k_scatter64(const int* __restrict__ src, const int* __restrict__ dst,
                            const float* __restrict__ norm, const float* __restrict__ h,
                            float* agg, int e) {
    int tid = blockIdx.x * blockDim.x + threadIdx.x;
    if (tid >= e * 16) return;
    int ed = tid >> 4;
    int j = tid & 15;
    int s = __ldg(&src[ed]);
    int d = __ldg(&dst[ed]);
    float w = __ldg(&norm[ed]);
    float4 v = ((const float4*)h)[s * 16 + j];
    redAdd4(agg + (size_t)d * 64 + j * 4, v.x * w, v.y * w, v.z * w, v.w * w);
}

// ---------------- transforms: h_out = silu(agg @ W + b); opt agg_next = h_out*dinv^2 ----------------
// DIN=16, DOUT in {16,64}. One thread per node, W cached in smem, fully unrolled.
template <int DOUT>
__global__ void k_transform16(const float* __restrict__ agg, const float* __restrict__ W,
                              const float* __restrict__ b, const float* __restrict__ dinv,
                              float* __restrict__ hout, float* __restrict__ aggout, int n) {
    __shared__ float4 sW4[16 * DOUT / 4];
    __shared__ float sB[DOUT];
    int tid = threadIdx.x;
    for (int k = tid; k < 16 * DOUT / 4; k += blockDim.x) sW4[k] = ((const float4*)W)[k];
    for (int k = tid; k < DOUT; k += blockDim.x) sB[k] = b[k];
    __syncthreads();
    int node = blockIdx.x * blockDim.x + tid;
    if (node >= n) return;

    const float4* A4 = (const float4*)(agg + (size_t)node * 16);
    float4 a0 = A4[0], a1 = A4[1], a2 = A4[2], a3 = A4[3];
    float av[16];
    av[0] = a0.x; av[1] = a0.y; av[2] = a0.z; av[3] = a0.w;
    av[4] = a1.x; av[5] = a1.y; av[6] = a1.z; av[7] = a1.w;
    av[8] = a2.x; av[9] = a2.y; av[10] = a2.z; av[11] = a2.w;
    av[12] = a3.x; av[13] = a3.y; av[14] = a3.z; av[15] = a3.w;

    float4 acc[DOUT / 4];
#pragma unroll
    for (int k = 0; k < DOUT / 4; k++) acc[k] = make_float4(0.f, 0.f, 0.f, 0.f);
#pragma unroll
    for (int i = 0; i < 16; i++) {
#pragma unroll
        for (int k = 0; k < DOUT / 4; k++) {
            float4 w = sW4[i * (DOUT / 4) + k];
            acc[k].x += av[i] * w.x;
            acc[k].y += av[i] * w.y;
            acc[k].z += av[i] * w.z;
            acc[k].w += av[i] * w.w;
        }
    }
    float d = dinv[node];
    float d2 = d * d;
    float4* H4 = (float4*)(hout + (size_t)node * DOUT);
    float4* G4 = aggout ? (float4*)(aggout + (size_t)node * DOUT) : nullptr;
#pragma unroll
    for (int k = 0; k < DOUT / 4; k++) {
        float4 v;
        v.x = silu(acc[k].x + sB[4 * k + 0]);
        v.y = silu(acc[k].y + sB[4 * k + 1]);
        v.z = silu(acc[k].z + sB[4 * k + 2]);
        v.w = silu(acc[k].w + sB[4 * k + 3]);
        H4[k] = v;
        if (G4) {
            float4 g = {v.x * d2, v.y * d2, v.z * d2, v.w * d2};
            G4[k] = g;
        }
    }
}

// DIN=64, DOUT=256. Block = 256 threads = 8 warps, 4 nodes/warp -> 32 nodes/block.
// Dynamic smem: W (64KB) + A tile (8KB) = 72KB.
__global__ void k_transform64_256(const float* __restrict__ agg, const float* __restrict__ W,
                                  const float* __restrict__ b, float* __restrict__ hout,
                                  int n) {
    extern __shared__ float smem[];
    float* sW = smem;             // 64*256
    float* sA = smem + 64 * 256;  // 32*64
    int tid = threadIdx.x;
    int lane = tid & 31;
    int warp = tid >> 5;
    int nodeBase = blockIdx.x * 32;

    const float4* W4 = (const float4*)W;
    float4* sW4 = (float4*)sW;
#pragma unroll
    for (int k = 0; k < 16; k++) sW4[tid + k * 256] = W4[tid + k * 256];
    const float4* A4 = (const float4*)(agg + (size_t)nodeBase * 64);
    float4* sA4 = (float4*)sA;
#pragma unroll
    for (int k = 0; k < 2; k++) sA4[tid + k * 256] = A4[tid + k * 256];
    __syncthreads();

    float acc[4][8];
#pragma unroll
    for (int j = 0; j < 4; j++)
#pragma unroll
        for (int k = 0; k < 8; k++) acc[j][k] = 0.f;

    int o0 = lane * 8;
#pragma unroll 8
    for (int i = 0; i < 64; i++) {
        float4 w0 = sW4[(i * 256 + o0) >> 2];
        float4 w1 = sW4[((i * 256 + o0) >> 2) + 1];
#pragma unroll
        for (int j = 0; j < 4; j++) {
            float a = sA[(warp * 4 + j) * 64 + i];
            acc[j][0] += a * w0.x;
            acc[j][1] += a * w0.y;
            acc[j][2] += a * w0.z;
            acc[j][3] += a * w0.w;
            acc[j][4] += a * w1.x;
            acc[j][5] += a * w1.y;
            acc[j][6] += a * w1.z;
            acc[j][7] += a * w1.w;
        }
    }

    float b0 = __ldg(&b[o0 + 0]), b1 = __ldg(&b[o0 + 1]), b2 = __ldg(&b[o0 + 2]),
          b3 = __ldg(&b[o0 + 3]), b4 = __ldg(&b[o0 + 4]), b5 = __ldg(&b[o0 + 5]),
          b6 = __ldg(&b[o0 + 6]), b7 = __ldg(&b[o0 + 7]);
#pragma unroll
    for (int j = 0; j < 4; j++) {
        int node = nodeBase + warp * 4 + j;
        if (node >= n) continue;
        float4 v0, v1;
        v0.x = silu(acc[j][0] + b0);
        v0.y = silu(acc[j][1] + b1);
        v0.z = silu(acc[j][2] + b2);
        v0.w = silu(acc[j][3] + b3);
        v1.x = silu(acc[j][4] + b4);
        v1.y = silu(acc[j][5] + b5);
        v1.z = silu(acc[j][6] + b6);
        v1.w = silu(acc[j][7] + b7);
        float4* H4 = (float4*)(hout + (size_t)node * 256 + o0);
        H4[0] = v0;
        H4[1] = v1;
    }
}

// ---------------- pool ----------------
__global__ void k_zero_pool(float* sums, float* cnt) {
    int i = blockIdx.x * blockDim.x + threadIdx.x;
    if (i < NG * 256) sums[i] = 0.f;
    if (i < NG) cnt[i] = 0.f;
}

__global__ void k_pool(const float* __restrict__ h3, const int* __restrict__ batch,
                       float* sums, float* cnt, int n) {
    int o = threadIdx.x;  // 256
    int n0 = blockIdx.x * 256;
    int nEnd = min(n0 + 256, n);
    if (n0 >= n) return;
    float acc = 0.f;
    int c = 0;
    int curg = __ldg(&batch[n0]);
    for (int nn = n0; nn < nEnd; nn++) {
        int g = __ldg(&batch[nn]);
        if (g != curg) {
            atomicAdd(&sums[curg * 256 + o], acc);
            if (o == 0) atomicAdd(&cnt[curg], (float)c);
            acc = 0.f;
            c = 0;
            curg = g;
        }
        acc += h3[(size_t)nn * 256 + o];
        c++;
    }
    atomicAdd(&sums[curg * 256 + o], acc);
    if (o == 0) atomicAdd(&cnt[curg], (float)c);
}

// ---------------- MLP head: one block per graph ----------------
__global__ void k_mlp(const float* __restrict__ sums, const float* __restrict__ cnt,
                      const float* __restrict__ L1, const float* __restrict__ c1,
                      const float* __restrict__ L2, const float* __restrict__ c2,
                      const float* __restrict__ L3, const float* __restrict__ c3,
                      float* __restrict__ out) {
    __shared__ float sp[256];
    __shared__ float s1[128];
    __shared__ float s2[64];
    int g = blockIdx.x;
    int t = threadIdx.x;  // 128
    float invc = 1.0f / fmaxf(cnt[g], 1.0f);
    sp[t] = sums[g * 256 + t] * invc;
    sp[t + 128] = sums[g * 256 + 128 + t] * invc;
    __syncthreads();
    {
        float acc = c1[t];
        for (int i = 0; i < 256; i++) acc += sp[i] * L1[i * 128 + t];
        s1[t] = silu(acc);
    }
    __syncthreads();
    if (t < 64) {
        float acc = c2[t];
        for (int i = 0; i < 128; i++) acc += s1[i] * L2[i * 64 + t];
        s2[t] = silu(acc);
    }
    __syncthreads();
    if (t < 3) {
        float acc = c3[t];
        for (int i = 0; i < 64; i++) acc += s2[i] * L3[i * 3 + t];
        out[g * 3 + t] = acc;
    }
}

// ---------------- launch ----------------
static void* sym(const void* s) {
    void* p = nullptr;
    cudaGetSymbolAddress(&p, s);
    return p;
}

extern "C" void kernel_launch(void* const* d_in, const int* in_sizes, int n_in,
                              void* d_out, int out_size) {
    const float* x = (const float*)d_in[0];
    const int* ei = (const int*)d_in[1];
    const float* ew = (const float*)d_in[2];
    const int* batch = (const int*)d_in[3];
    const float* W1 = (const float*)d_in[4];
    const float* b1 = (const float*)d_in[5];
    const float* W2 = (const float*)d_in[6];
    const float* b2 = (const float*)d_in[7];
    const float* W3 = (const float*)d_in[8];
    const float* b3 = (const float*)d_in[9];
    const float* L1 = (const float*)d_in[10];
    const float* c1 = (const float*)d_in[11];
    const float* L2 = (const float*)d_in[12];
    const float* c2 = (const float*)d_in[13];
    const float* L3 = (const float*)d_in[14];
    const float* c3 = (const float*)d_in[15];
    float* out = (float*)d_out;

    const int N = in_sizes[0] / 16;  // 100000
    const int E = in_sizes[2];       // 3200000
    const int* src = ei;
    const int* dst = ei + E;

    float* deg = (float*)sym(g_deg);
    float* dinv = (float*)sym(g_dinv);
    float* norm = (float*)sym(g_norm);
    float* agg1 = (float*)sym(g_agg1);
    float* h1 = (float*)sym(g_h1);
    float* agg2 = (float*)sym(g_agg2);
    float* h2 = (float*)sym(g_h2);
    float* agg3 = (float*)sym(g_agg3);
    float* h3 = (float*)sym(g_h3);
    float* sums = (float*)sym(g_sums);
    float* cnt = (float*)sym(g_cnt);

    const int T = 256;
    int gn = (N + T - 1) / T;
    int ge = (E + T - 1) / T;

    // degree + norm
    k_deg_init<<<gn, T>>>(deg, N);
    k_deg_acc<<<ge, T>>>(dst, ew, deg, E);
    k_dinv<<<gn, T>>>(deg, dinv, N);
    k_norm<<<ge, T>>>(src, dst, ew, dinv, norm, E);

    // layer 1 (16 -> 16)
    k_agg1_init<<<(N * 4 + T - 1) / T, T>>>(x, dinv, agg1, N);
    k_scatter16<<<(E * 4 + T - 1) / T, T>>>(src, dst, norm, x, agg1, E);
    k_transform16<16><<<gn, T>>>(agg1, W1, b1, dinv, h1, agg2, N);

    // layer 2 (16 -> 64)
    k_scatter16<<<(E * 4 + T - 1) / T, T>>>(src, dst, norm, h1, agg2, E);
    k_transform16<64><<<gn, T>>>(agg2, W2, b2, dinv, h2, agg3, N);

    // layer 3 (64 -> 256)
    k_scatter64<<<(E * 16 + T - 1) / T, T>>>(src, dst, norm, h2, agg3, E);
    {
        int smemBytes = (64 * 256 + 32 * 64) * (int)sizeof(float);  // 72KB
        cudaFuncSetAttribute(k_transform64_256,
                             cudaFuncAttributeMaxDynamicSharedMemorySize, smemBytes);
        int blocks = (N + 31) / 32;
        k_transform64_256<<<blocks, 256, smemBytes>>>(agg3, W3, b3, h3, N);
    }

    // pool + MLP
    k_zero_pool<<<(NG * 256 + T - 1) / T, T>>>(sums, cnt);
    k_pool<<<(N + 255) / 256, 256>>>(h3, batch, sums, cnt, N);
    k_mlp<<<NG, 128>>>(sums, cnt, L1, c1, L2, c2, L3, c3, out);
}